// round 12
// baseline (speedup 1.0000x reference)
#include <cuda_runtime.h>
#include <cuda_fp16.h>

#define N_VUL 100000
#define N_SRC 50000
#define N_EDGE 500000
#define D 128
#define NREL 3
#define CAP 64            // max in-degree per (rel,dst). Poisson(5): P(>32)~1e-18.

#define FILL_BLOCKS 977
#define CONV_BLOCKS 2048

// Static scratch (allocation is forbidden).
__device__ int g_cur[NREL][N_VUL];              // per-(rel,dst) cursor == in-degree
__device__ int g_bucket[NREL][N_VUL][CAP];      // src ids per (rel,dst)  (76.8 MB)
__device__ __half g_xh[NREL][N_SRC][D];         // fp16 mirror of x tables (38.4 MB)

__global__ void zero_cursors() {
    const int tid    = blockIdx.x * blockDim.x + threadIdx.x;
    const int stride = gridDim.x * blockDim.x;
    int* cur = &g_cur[0][0];
    for (int i = tid; i < NREL * N_VUL; i += stride) cur[i] = 0;
}

// Fused kernel: blocks [0, FILL_BLOCKS) bucketize edges (atomic-latency-bound);
// blocks [FILL_BLOCKS, ...) convert x tables to fp16 (bandwidth-bound).
__global__ void fill_convert_kernel(const int* __restrict__ sa, const int* __restrict__ da,
                                    const int* __restrict__ sb, const int* __restrict__ db,
                                    const int* __restrict__ sc, const int* __restrict__ dc,
                                    const float4* __restrict__ xa,
                                    const float4* __restrict__ xb,
                                    const float4* __restrict__ xc) {
    if (blockIdx.x < FILL_BLOCKS) {
        const int tid    = blockIdx.x * blockDim.x + threadIdx.x;
        const int stride = FILL_BLOCKS * blockDim.x;
        for (int e = tid; e < N_EDGE; e += stride) {
            int d, p;
            d = da[e]; p = atomicAdd(&g_cur[0][d], 1); if (p < CAP) g_bucket[0][d][p] = sa[e];
            d = db[e]; p = atomicAdd(&g_cur[1][d], 1); if (p < CAP) g_bucket[1][d][p] = sb[e];
            d = dc[e]; p = atomicAdd(&g_cur[2][d], 1); if (p < CAP) g_bucket[2][d][p] = sc[e];
        }
    } else {
        const int tid    = (blockIdx.x - FILL_BLOCKS) * blockDim.x + threadIdx.x;
        const int stride = CONV_BLOCKS * blockDim.x;
        const int n4 = N_SRC * D / 4;                 // 1.6M float4 per table
        const float4* __restrict__ xs[NREL] = { xa, xb, xc };
#pragma unroll
        for (int r = 0; r < NREL; r++) {
            const float4* __restrict__ x = xs[r];
            uint2* __restrict__ dst = (uint2*)&g_xh[r][0][0];
            for (int i = tid; i < n4; i += stride) {
                const float4 v = x[i];
                __half2 h0 = __floats2half2_rn(v.x, v.y);
                __half2 h1 = __floats2half2_rn(v.z, v.w);
                uint2 packed;
                packed.x = *(const unsigned int*)&h0;
                packed.y = *(const unsigned int*)&h1;
                dst[i] = packed;
            }
        }
    }
}

// Process up to n (<=32) edges, TWO per iteration: half-warp per edge.
// Lane = 16*g + h: group g in {0,1} handles edge 2i+g, sub-lane h owns
// halves [8h, 8h+8) of the 256B fp16 row via one LDG.128.
// Weight w (= recip of this relation) applied per-edge as FMA; invalid slots
// get weight 0 (their shfl'd src defaults to row 0 -> harmless load).
__device__ __forceinline__ void batch_sum2(const uint4* __restrict__ xh,
                                           int myidx, int n, int h, int g, float w,
                                           float4& lo, float4& hi) {
    const int iters = (n + 1) >> 1;
#pragma unroll 4
    for (int i = 0; i < iters; i++) {
        const int eidx = 2 * i + g;                       // <= 31 always
        const int s  = __shfl_sync(0xFFFFFFFFu, myidx, eidx);
        const float wt = (eidx < n) ? w : 0.0f;
        const uint4 hv = xh[s * (D / 8) + h];             // 8 halves
        const float2 f0 = __half22float2(*(const __half2*)&hv.x);
        const float2 f1 = __half22float2(*(const __half2*)&hv.y);
        const float2 f2 = __half22float2(*(const __half2*)&hv.z);
        const float2 f3 = __half22float2(*(const __half2*)&hv.w);
        lo.x = fmaf(f0.x, wt, lo.x); lo.y = fmaf(f0.y, wt, lo.y);
        lo.z = fmaf(f1.x, wt, lo.z); lo.w = fmaf(f1.y, wt, lo.w);
        hi.x = fmaf(f2.x, wt, hi.x); hi.y = fmaf(f2.y, wt, hi.y);
        hi.z = fmaf(f3.x, wt, hi.z); hi.w = fmaf(f3.y, wt, hi.w);
    }
}

// One warp per destination row, 2 edges in flight per iteration.
// Metadata (3 counts + 3 first-batch entry loads) hoisted (R9 win).
__global__ void pull_kernel(float4* __restrict__ out) {
    const int gtid = blockIdx.x * blockDim.x + threadIdx.x;
    const int dst  = gtid >> 5;
    const int lane = gtid & 31;
    if (dst >= N_VUL) return;

    const int h = lane & 15;       // sub-lane within half-warp (column group)
    const int g = lane >> 4;       // edge-group selector

    // 3 independent count loads.
    const int cf0 = g_cur[0][dst];
    const int cf1 = g_cur[1][dst];
    const int cf2 = g_cur[2][dst];
    const int c0 = cf0 < CAP ? cf0 : CAP;
    const int c1 = cf1 < CAP ? cf1 : CAP;
    const int c2 = cf2 < CAP ? cf2 : CAP;

    const int* __restrict__ b0 = g_bucket[0][dst];
    const int* __restrict__ b1 = g_bucket[1][dst];
    const int* __restrict__ b2 = g_bucket[2][dst];

    // 3 independent first-batch entry loads (lane e holds edge e's src id).
    const int my0 = (lane < c0) ? b0[lane] : 0;
    const int my1 = (lane < c1) ? b1[lane] : 0;
    const int my2 = (lane < c2) ? b2[lane] : 0;

    const float r0 = 1.0f / (3.0f * (float)(cf0 > 0 ? cf0 : 1));
    const float r1 = 1.0f / (3.0f * (float)(cf1 > 0 ? cf1 : 1));
    const float r2 = 1.0f / (3.0f * (float)(cf2 > 0 ? cf2 : 1));

    const uint4* __restrict__ xh0 = (const uint4*)&g_xh[0][0][0];
    const uint4* __restrict__ xh1 = (const uint4*)&g_xh[1][0][0];
    const uint4* __restrict__ xh2 = (const uint4*)&g_xh[2][0][0];

    float4 lo = make_float4(0.f, 0.f, 0.f, 0.f);
    float4 hi = make_float4(0.f, 0.f, 0.f, 0.f);

    // relation 0 (recip folded into per-edge FMA weight)
    batch_sum2(xh0, my0, c0 < 32 ? c0 : 32, h, g, r0, lo, hi);
    for (int base = 32; base < c0; base += 32) {              // cold path
        int mi = (base + lane < c0) ? b0[base + lane] : 0;
        batch_sum2(xh0, mi, (c0 - base) < 32 ? (c0 - base) : 32, h, g, r0, lo, hi);
    }
    // relation 1
    batch_sum2(xh1, my1, c1 < 32 ? c1 : 32, h, g, r1, lo, hi);
    for (int base = 32; base < c1; base += 32) {
        int mi = (base + lane < c1) ? b1[base + lane] : 0;
        batch_sum2(xh1, mi, (c1 - base) < 32 ? (c1 - base) : 32, h, g, r1, lo, hi);
    }
    // relation 2
    batch_sum2(xh2, my2, c2 < 32 ? c2 : 32, h, g, r2, lo, hi);
    for (int base = 32; base < c2; base += 32) {
        int mi = (base + lane < c2) ? b2[base + lane] : 0;
        batch_sum2(xh2, mi, (c2 - base) < 32 ? (c2 - base) : 32, h, g, r2, lo, hi);
    }

    // Combine the two edge-groups: lanes l and l+16 hold the same columns.
    lo.x += __shfl_xor_sync(0xFFFFFFFFu, lo.x, 16);
    lo.y += __shfl_xor_sync(0xFFFFFFFFu, lo.y, 16);
    lo.z += __shfl_xor_sync(0xFFFFFFFFu, lo.z, 16);
    lo.w += __shfl_xor_sync(0xFFFFFFFFu, lo.w, 16);
    hi.x += __shfl_xor_sync(0xFFFFFFFFu, hi.x, 16);
    hi.y += __shfl_xor_sync(0xFFFFFFFFu, hi.y, 16);
    hi.z += __shfl_xor_sync(0xFFFFFFFFu, hi.z, 16);
    hi.w += __shfl_xor_sync(0xFFFFFFFFu, hi.w, 16);

    // Lane 16*g+h stores float4 (2h+g) of the row: cols [8h+4g, 8h+4g+4).
    out[dst * (D / 4) + 2 * h + g] = (g == 0) ? lo : hi;
}

extern "C" void kernel_launch(void* const* d_in, const int* in_sizes, int n_in,
                              void* d_out, int out_size) {
    // metadata order: x_a, x_b, x_c, src_a, dst_a, src_b, dst_b, src_c, dst_c
    const float* xa = (const float*)d_in[0];
    const float* xb = (const float*)d_in[1];
    const float* xc = (const float*)d_in[2];
    const int* sa = (const int*)d_in[3];
    const int* da = (const int*)d_in[4];
    const int* sb = (const int*)d_in[5];
    const int* db = (const int*)d_in[6];
    const int* sc = (const int*)d_in[7];
    const int* dc = (const int*)d_in[8];
    float* out = (float*)d_out;

    zero_cursors<<<296, 256>>>();
    fill_convert_kernel<<<FILL_BLOCKS + CONV_BLOCKS, 256>>>(
        sa, da, sb, db, sc, dc,
        (const float4*)xa, (const float4*)xb, (const float4*)xc);

    // 100000 dsts * 32 threads = 3.2M threads; 8 warps/block -> 12500 blocks
    pull_kernel<<<12500, 256>>>((float4*)out);
}

// round 13
// speedup vs baseline: 1.0569x; 1.0569x over previous
#include <cuda_runtime.h>
#include <cuda_fp16.h>

#define N_VUL 100000
#define N_SRC 50000
#define N_EDGE 500000
#define D 128
#define NREL 3
#define CAP 64            // max in-degree per (rel,dst). Poisson(5): P(>32)~1e-18.

#define FILL_BLOCKS 977
#define CONV_BLOCKS 2048

// Static scratch (allocation is forbidden).
// Self-cleaning invariant: g_cur is all-zero at entry to every kernel_launch
// (zero-initialized at module load; pull_kernel's end-of-block sweep re-zeroes
// exactly the entries it read, after __syncthreads).
__device__ int g_cur[NREL][N_VUL];              // per-(rel,dst) cursor == in-degree
__device__ int g_bucket[NREL][N_VUL][CAP];      // src ids per (rel,dst)  (76.8 MB)
__device__ __half g_xh[NREL][N_SRC][D];         // fp16 mirror of x tables (38.4 MB)

// Fused kernel: blocks [0, FILL_BLOCKS) bucketize edges (atomic-latency-bound);
// blocks [FILL_BLOCKS, ...) convert x tables to fp16 (bandwidth-bound).
__global__ void fill_convert_kernel(const int* __restrict__ sa, const int* __restrict__ da,
                                    const int* __restrict__ sb, const int* __restrict__ db,
                                    const int* __restrict__ sc, const int* __restrict__ dc,
                                    const float4* __restrict__ xa,
                                    const float4* __restrict__ xb,
                                    const float4* __restrict__ xc) {
    if (blockIdx.x < FILL_BLOCKS) {
        const int tid    = blockIdx.x * blockDim.x + threadIdx.x;
        const int stride = FILL_BLOCKS * blockDim.x;
        for (int e = tid; e < N_EDGE; e += stride) {
            int d, p;
            d = da[e]; p = atomicAdd(&g_cur[0][d], 1); if (p < CAP) g_bucket[0][d][p] = sa[e];
            d = db[e]; p = atomicAdd(&g_cur[1][d], 1); if (p < CAP) g_bucket[1][d][p] = sb[e];
            d = dc[e]; p = atomicAdd(&g_cur[2][d], 1); if (p < CAP) g_bucket[2][d][p] = sc[e];
        }
    } else {
        const int tid    = (blockIdx.x - FILL_BLOCKS) * blockDim.x + threadIdx.x;
        const int stride = CONV_BLOCKS * blockDim.x;
        const int n4 = N_SRC * D / 4;                 // 1.6M float4 per table
        const float4* __restrict__ xs[NREL] = { xa, xb, xc };
#pragma unroll
        for (int r = 0; r < NREL; r++) {
            const float4* __restrict__ x = xs[r];
            uint2* __restrict__ dst = (uint2*)&g_xh[r][0][0];
            for (int i = tid; i < n4; i += stride) {
                const float4 v = x[i];
                __half2 h0 = __floats2half2_rn(v.x, v.y);
                __half2 h1 = __floats2half2_rn(v.z, v.w);
                uint2 packed;
                packed.x = *(const unsigned int*)&h0;
                packed.y = *(const unsigned int*)&h1;
                dst[i] = packed;
            }
        }
    }
}

// Sum up to n (<=32) gathered fp16 rows (fp32 accumulate). Proven R10 inner
// loop shape: shfl broadcast + unroll 4, 8B loads. FROZEN — do not restructure.
__device__ __forceinline__ float4 batch_sum(const uint2* __restrict__ xh,
                                            int myidx, int n, int lane, float4 a) {
#pragma unroll 4
    for (int e = 0; e < n; e++) {
        const int s = __shfl_sync(0xFFFFFFFFu, myidx, e);
        const uint2 h = xh[s * (D / 4) + lane];       // 4 halves: cols 4*lane..+3
        const float2 f0 = __half22float2(*(const __half2*)&h.x);
        const float2 f1 = __half22float2(*(const __half2*)&h.y);
        a.x += f0.x; a.y += f0.y; a.z += f1.x; a.w += f1.y;
    }
    return a;
}

// One warp per destination row. Lane l owns float cols [4l, 4l+4).
// Hot path byte-identical to the proven 62.4us R10 kernel. At the end, the
// block (8 warps == dsts [8b, 8b+8), grid covers N_VUL exactly) zeroes the
// 24 cursor entries it read, replacing the zero_cursors launch.
__global__ void pull_kernel(float4* __restrict__ out) {
    const int gtid = blockIdx.x * blockDim.x + threadIdx.x;
    const int dst  = gtid >> 5;
    const int lane = gtid & 31;
    // grid is sized so dst < N_VUL always (12500 blocks * 8 warps == N_VUL).

    // 3 independent count loads.
    const int cf0 = g_cur[0][dst];
    const int cf1 = g_cur[1][dst];
    const int cf2 = g_cur[2][dst];
    const int c0 = cf0 < CAP ? cf0 : CAP;
    const int c1 = cf1 < CAP ? cf1 : CAP;
    const int c2 = cf2 < CAP ? cf2 : CAP;

    const int* __restrict__ b0 = g_bucket[0][dst];
    const int* __restrict__ b1 = g_bucket[1][dst];
    const int* __restrict__ b2 = g_bucket[2][dst];

    // 3 independent first-batch entry loads.
    const int my0 = (lane < c0) ? b0[lane] : 0;
    const int my1 = (lane < c1) ? b1[lane] : 0;
    const int my2 = (lane < c2) ? b2[lane] : 0;

    const uint2* __restrict__ xh0 = (const uint2*)&g_xh[0][0][0];
    const uint2* __restrict__ xh1 = (const uint2*)&g_xh[1][0][0];
    const uint2* __restrict__ xh2 = (const uint2*)&g_xh[2][0][0];

    float4 acc = make_float4(0.f, 0.f, 0.f, 0.f);

    // relation 0
    {
        float4 a = make_float4(0.f, 0.f, 0.f, 0.f);
        a = batch_sum(xh0, my0, c0 < 32 ? c0 : 32, lane, a);
        for (int base = 32; base < c0; base += 32) {          // cold path
            int mi = (base + lane < c0) ? b0[base + lane] : 0;
            a = batch_sum(xh0, mi, (c0 - base) < 32 ? (c0 - base) : 32, lane, a);
        }
        const float recip = 1.0f / (3.0f * (float)(cf0 > 0 ? cf0 : 1));
        acc.x += a.x * recip; acc.y += a.y * recip;
        acc.z += a.z * recip; acc.w += a.w * recip;
    }
    // relation 1
    {
        float4 a = make_float4(0.f, 0.f, 0.f, 0.f);
        a = batch_sum(xh1, my1, c1 < 32 ? c1 : 32, lane, a);
        for (int base = 32; base < c1; base += 32) {          // cold path
            int mi = (base + lane < c1) ? b1[base + lane] : 0;
            a = batch_sum(xh1, mi, (c1 - base) < 32 ? (c1 - base) : 32, lane, a);
        }
        const float recip = 1.0f / (3.0f * (float)(cf1 > 0 ? cf1 : 1));
        acc.x += a.x * recip; acc.y += a.y * recip;
        acc.z += a.z * recip; acc.w += a.w * recip;
    }
    // relation 2
    {
        float4 a = make_float4(0.f, 0.f, 0.f, 0.f);
        a = batch_sum(xh2, my2, c2 < 32 ? c2 : 32, lane, a);
        for (int base = 32; base < c2; base += 32) {          // cold path
            int mi = (base + lane < c2) ? b2[base + lane] : 0;
            a = batch_sum(xh2, mi, (c2 - base) < 32 ? (c2 - base) : 32, lane, a);
        }
        const float recip = 1.0f / (3.0f * (float)(cf2 > 0 ? cf2 : 1));
        acc.x += a.x * recip; acc.y += a.y * recip;
        acc.z += a.z * recip; acc.w += a.w * recip;
    }

    out[dst * (D / 4) + lane] = acc;

    // ---- self-clean sweep (replaces zero_cursors kernel) ----
    // All 8 warps of this block have finished reading their g_cur entries.
    __syncthreads();
    const int t = threadIdx.x;
    if (t < NREL * 8) {                    // 24 entries: 3 rels x 8 dsts
        const int rel = t >> 3;
        const int d   = (blockIdx.x << 3) + (t & 7);
        g_cur[rel][d] = 0;
    }
}

extern "C" void kernel_launch(void* const* d_in, const int* in_sizes, int n_in,
                              void* d_out, int out_size) {
    // metadata order: x_a, x_b, x_c, src_a, dst_a, src_b, dst_b, src_c, dst_c
    const float* xa = (const float*)d_in[0];
    const float* xb = (const float*)d_in[1];
    const float* xc = (const float*)d_in[2];
    const int* sa = (const int*)d_in[3];
    const int* da = (const int*)d_in[4];
    const int* sb = (const int*)d_in[5];
    const int* db = (const int*)d_in[6];
    const int* sc = (const int*)d_in[7];
    const int* dc = (const int*)d_in[8];
    float* out = (float*)d_out;

    fill_convert_kernel<<<FILL_BLOCKS + CONV_BLOCKS, 256>>>(
        sa, da, sb, db, sc, dc,
        (const float4*)xa, (const float4*)xb, (const float4*)xc);

    // 100000 dsts * 32 threads = 3.2M threads; 8 warps/block -> 12500 blocks
    pull_kernel<<<12500, 256>>>((float4*)out);
}

// round 14
// speedup vs baseline: 1.1584x; 1.0961x over previous
#include <cuda_runtime.h>
#include <cuda_fp16.h>

#define N_VUL 100000
#define N_SRC 50000
#define N_EDGE 500000
#define D 128
#define NREL 3
#define CAP 64            // max in-degree per (rel,dst). Poisson(5): P(>32)~1e-18.

#define FILL_BLOCKS 977
#define CONV_BLOCKS 2048

// Static scratch (allocation is forbidden).
__device__ int g_cur[NREL][N_VUL];              // per-(rel,dst) cursor == in-degree
__device__ int g_bucket[NREL][N_VUL][CAP];      // src ids per (rel,dst)  (76.8 MB)
__device__ __half g_xh[NREL][N_SRC][D];         // fp16 mirror of x tables (38.4 MB)

__global__ void zero_cursors() {
    const int tid    = blockIdx.x * blockDim.x + threadIdx.x;
    const int stride = gridDim.x * blockDim.x;
    int* cur = &g_cur[0][0];
    for (int i = tid; i < NREL * N_VUL; i += stride) cur[i] = 0;
}

// Fused kernel: blocks [0, FILL_BLOCKS) bucketize edges (atomic-latency-bound);
// blocks [FILL_BLOCKS, ...) convert x tables to fp16 (bandwidth-bound).
__global__ void fill_convert_kernel(const int* __restrict__ sa, const int* __restrict__ da,
                                    const int* __restrict__ sb, const int* __restrict__ db,
                                    const int* __restrict__ sc, const int* __restrict__ dc,
                                    const float4* __restrict__ xa,
                                    const float4* __restrict__ xb,
                                    const float4* __restrict__ xc) {
    if (blockIdx.x < FILL_BLOCKS) {
        const int tid    = blockIdx.x * blockDim.x + threadIdx.x;
        const int stride = FILL_BLOCKS * blockDim.x;
        for (int e = tid; e < N_EDGE; e += stride) {
            int d, p;
            d = da[e]; p = atomicAdd(&g_cur[0][d], 1); if (p < CAP) g_bucket[0][d][p] = sa[e];
            d = db[e]; p = atomicAdd(&g_cur[1][d], 1); if (p < CAP) g_bucket[1][d][p] = sb[e];
            d = dc[e]; p = atomicAdd(&g_cur[2][d], 1); if (p < CAP) g_bucket[2][d][p] = sc[e];
        }
    } else {
        const int tid    = (blockIdx.x - FILL_BLOCKS) * blockDim.x + threadIdx.x;
        const int stride = CONV_BLOCKS * blockDim.x;
        const int n4 = N_SRC * D / 4;                 // 1.6M float4 per table
        const float4* __restrict__ xs[NREL] = { xa, xb, xc };
#pragma unroll
        for (int r = 0; r < NREL; r++) {
            const float4* __restrict__ x = xs[r];
            uint2* __restrict__ dst = (uint2*)&g_xh[r][0][0];
            for (int i = tid; i < n4; i += stride) {
                const float4 v = x[i];
                __half2 h0 = __floats2half2_rn(v.x, v.y);
                __half2 h1 = __floats2half2_rn(v.z, v.w);
                uint2 packed;
                packed.x = *(const unsigned int*)&h0;
                packed.y = *(const unsigned int*)&h1;
                dst[i] = packed;
            }
        }
    }
}

// Sum up to n (<=32) gathered fp16 rows (fp32 accumulate). Proven R10 inner
// loop shape: shfl broadcast + unroll 4, 8B loads. FROZEN — do not restructure.
__device__ __forceinline__ float4 batch_sum(const uint2* __restrict__ xh,
                                            int myidx, int n, int lane, float4 a) {
#pragma unroll 4
    for (int e = 0; e < n; e++) {
        const int s = __shfl_sync(0xFFFFFFFFu, myidx, e);
        const uint2 h = xh[s * (D / 4) + lane];       // 4 halves: cols 4*lane..+3
        const float2 f0 = __half22float2(*(const __half2*)&h.x);
        const float2 f1 = __half22float2(*(const __half2*)&h.y);
        a.x += f0.x; a.y += f0.y; a.z += f1.x; a.w += f1.y;
    }
    return a;
}

// One warp per destination row. Lane l owns float cols [4l, 4l+4).
// Hot path identical to the proven 62.4us R10 kernel; only cache-policy hints
// added: __ldcs on read-once bucket entries, __stcs on the write-once output.
__global__ void pull_kernel(float4* __restrict__ out) {
    const int gtid = blockIdx.x * blockDim.x + threadIdx.x;
    const int dst  = gtid >> 5;
    const int lane = gtid & 31;
    if (dst >= N_VUL) return;

    // 3 independent count loads.
    const int cf0 = g_cur[0][dst];
    const int cf1 = g_cur[1][dst];
    const int cf2 = g_cur[2][dst];
    const int c0 = cf0 < CAP ? cf0 : CAP;
    const int c1 = cf1 < CAP ? cf1 : CAP;
    const int c2 = cf2 < CAP ? cf2 : CAP;

    const int* __restrict__ b0 = g_bucket[0][dst];
    const int* __restrict__ b1 = g_bucket[1][dst];
    const int* __restrict__ b2 = g_bucket[2][dst];

    // 3 independent first-batch entry loads (read-once -> evict-first).
    const int my0 = (lane < c0) ? __ldcs(&b0[lane]) : 0;
    const int my1 = (lane < c1) ? __ldcs(&b1[lane]) : 0;
    const int my2 = (lane < c2) ? __ldcs(&b2[lane]) : 0;

    const uint2* __restrict__ xh0 = (const uint2*)&g_xh[0][0][0];
    const uint2* __restrict__ xh1 = (const uint2*)&g_xh[1][0][0];
    const uint2* __restrict__ xh2 = (const uint2*)&g_xh[2][0][0];

    float4 acc = make_float4(0.f, 0.f, 0.f, 0.f);

    // relation 0
    {
        float4 a = make_float4(0.f, 0.f, 0.f, 0.f);
        a = batch_sum(xh0, my0, c0 < 32 ? c0 : 32, lane, a);
        for (int base = 32; base < c0; base += 32) {          // cold path
            int mi = (base + lane < c0) ? __ldcs(&b0[base + lane]) : 0;
            a = batch_sum(xh0, mi, (c0 - base) < 32 ? (c0 - base) : 32, lane, a);
        }
        const float recip = 1.0f / (3.0f * (float)(cf0 > 0 ? cf0 : 1));
        acc.x += a.x * recip; acc.y += a.y * recip;
        acc.z += a.z * recip; acc.w += a.w * recip;
    }
    // relation 1
    {
        float4 a = make_float4(0.f, 0.f, 0.f, 0.f);
        a = batch_sum(xh1, my1, c1 < 32 ? c1 : 32, lane, a);
        for (int base = 32; base < c1; base += 32) {          // cold path
            int mi = (base + lane < c1) ? __ldcs(&b1[base + lane]) : 0;
            a = batch_sum(xh1, mi, (c1 - base) < 32 ? (c1 - base) : 32, lane, a);
        }
        const float recip = 1.0f / (3.0f * (float)(cf1 > 0 ? cf1 : 1));
        acc.x += a.x * recip; acc.y += a.y * recip;
        acc.z += a.z * recip; acc.w += a.w * recip;
    }
    // relation 2
    {
        float4 a = make_float4(0.f, 0.f, 0.f, 0.f);
        a = batch_sum(xh2, my2, c2 < 32 ? c2 : 32, lane, a);
        for (int base = 32; base < c2; base += 32) {          // cold path
            int mi = (base + lane < c2) ? __ldcs(&b2[base + lane]) : 0;
            a = batch_sum(xh2, mi, (c2 - base) < 32 ? (c2 - base) : 32, lane, a);
        }
        const float recip = 1.0f / (3.0f * (float)(cf2 > 0 ? cf2 : 1));
        acc.x += a.x * recip; acc.y += a.y * recip;
        acc.z += a.z * recip; acc.w += a.w * recip;
    }

    // Write-once output: streaming store keeps g_xh resident in L2.
    __stcs(&out[dst * (D / 4) + lane], acc);
}

extern "C" void kernel_launch(void* const* d_in, const int* in_sizes, int n_in,
                              void* d_out, int out_size) {
    // metadata order: x_a, x_b, x_c, src_a, dst_a, src_b, dst_b, src_c, dst_c
    const float* xa = (const float*)d_in[0];
    const float* xb = (const float*)d_in[1];
    const float* xc = (const float*)d_in[2];
    const int* sa = (const int*)d_in[3];
    const int* da = (const int*)d_in[4];
    const int* sb = (const int*)d_in[5];
    const int* db = (const int*)d_in[6];
    const int* sc = (const int*)d_in[7];
    const int* dc = (const int*)d_in[8];
    float* out = (float*)d_out;

    zero_cursors<<<296, 256>>>();
    fill_convert_kernel<<<FILL_BLOCKS + CONV_BLOCKS, 256>>>(
        sa, da, sb, db, sc, dc,
        (const float4*)xa, (const float4*)xb, (const float4*)xc);

    // 100000 dsts * 32 threads = 3.2M threads; 8 warps/block -> 12500 blocks
    pull_kernel<<<12500, 256>>>((float4*)out);
}